// round 13
// baseline (speedup 1.0000x reference)
#include <cuda_runtime.h>
#include <cuda_fp16.h>
#include <math.h>
#include <stdint.h>

#define NN 16384
#define NE 32
#define NH 256
#define OUTD 5

typedef __half fp16;

// ---------------- scratch (device globals) ----------------
__device__ __align__(16) float g_cvec[256];
__device__ __align__(16) float g_V[NN * NH];
__device__ __align__(16) float g_z[NN * NH];

__device__ __align__(16) fp16 g_Mt_hi[256 * 256], g_Mt_lo[256 * 256];
__device__ __align__(16) fp16 g_in1_hi[NN * 512], g_in1_lo[NN * 512];  // [th || Hagg]
__device__ __align__(16) fp16 g_cat[NN * 512];                          // [x_e || H_e]
__device__ __align__(16) fp16 g_prev[NN * 256];
__device__ __align__(16) fp16 g_rh[NN * 256];
__device__ __align__(16) fp16 g_Whe[256 * 512];
__device__ __align__(16) fp16 g_Uzr[512 * 768];
__device__ __align__(16) fp16 g_Un[256 * 768];

// ---------------- PTX helpers ----------------
__device__ __forceinline__ uint32_t smem_u32(const void* p) {
    uint32_t a;
    asm("{ .reg .u64 t; cvta.to.shared.u64 t, %1; cvt.u32.u64 %0, t; }" : "=r"(a) : "l"(p));
    return a;
}
__device__ __forceinline__ void cp_async16(uint32_t s, const void* g) {
    asm volatile("cp.async.cg.shared.global [%0], [%1], 16;" :: "r"(s), "l"(g) : "memory");
}
__device__ __forceinline__ void cp_commit() {
    asm volatile("cp.async.commit_group;" ::: "memory");
}
__device__ __forceinline__ void ldmx4(uint32_t* r, uint32_t addr) {
    asm volatile("ldmatrix.sync.aligned.m8n8.x4.shared.b16 {%0,%1,%2,%3}, [%4];"
                 : "=r"(r[0]), "=r"(r[1]), "=r"(r[2]), "=r"(r[3]) : "r"(addr));
}
__device__ __forceinline__ void mma16816(float* c, const uint32_t* a, uint32_t b0, uint32_t b1) {
    asm volatile(
        "mma.sync.aligned.m16n8k16.row.col.f32.f16.f16.f32 "
        "{%0,%1,%2,%3}, {%4,%5,%6,%7}, {%8,%9}, {%0,%1,%2,%3};"
        : "+f"(c[0]), "+f"(c[1]), "+f"(c[2]), "+f"(c[3])
        : "r"(a[0]), "r"(a[1]), "r"(a[2]), "r"(a[3]), "r"(b0), "r"(b1));
}
__device__ __forceinline__ void split_write(fp16* hi, fp16* lo, size_t off, float x) {
    fp16 h = __float2half_rn(x);
    hi[off] = h;
    lo[off] = __float2half_rn(x - __half2float(h));
}

// ---------------- fp16 split GEMM: BM=BN=128, 256 thr, 2 CTA/SM ----------
// NTERMS=3: BK=32, A(hi,lo) x W(hi,lo), 2-stage (40KB/stage), pitch 80.
// NTERMS=1: BK=64, A x W single, 3-stage (36.9KB/stage), pitch 144,
//           register double-buffered fragments (LDSM latency hidden).
// OUTMODE: 2 = relu + fp16; 3 = zr epilogue; 4 = n/final + fused predict; 5 = fp32+bias.
template <int OUTMODE, int NTERMS>
__global__ void __launch_bounds__(256, 2) mma3(
    const fp16* __restrict__ A1h, const fp16* __restrict__ A1l, int lda1,
    const fp16* __restrict__ A2h, const fp16* __restrict__ A2l, int lda2, int splitK,
    const fp16* __restrict__ Wh, const fp16* __restrict__ Wl, int ldw, int K,
    fp16* __restrict__ Cout, int ldc, int coff,
    const float* __restrict__ bg, const float* __restrict__ prevp,
    float* __restrict__ zbuf,
    fp16* __restrict__ rhout,
    float* __restrict__ outh,
    const float* __restrict__ Wp, float* __restrict__ predout)
{
    constexpr int BK = (NTERMS == 1) ? 64 : 32;
    constexpr uint32_t PITCH = (NTERMS == 1) ? 144u : 80u;
    constexpr uint32_t TILE = 128u * PITCH;
    constexpr uint32_t ST = (NTERMS == 3) ? 4 * TILE : TILE * 2;
    constexpr int STAGES = (NTERMS == 3) ? 2 : 3;
    constexpr int CPR = BK / 8;
    constexpr uint32_t WOFF = (NTERMS == 1) ? TILE : 2 * TILE;
    extern __shared__ char sm[];
    const uint32_t base = smem_u32(sm);
    const int t = threadIdx.x, wid = t >> 5, lane = t & 31;
    const int wm = wid & 1, wn = wid >> 1;
    const int row0 = blockIdx.y * 128, col0 = blockIdx.x * 128;
    const int chunks = K / BK;

    auto load_stage = [&](int s, int ck) {
        int k0 = ck * BK;
        const fp16 *ah, *al;
        int lda, kk;
        if (k0 < splitK) { ah = A1h; al = A1l; lda = lda1; kk = k0; }
        else             { ah = A2h; al = A2l; lda = lda2; kk = k0 - splitK; }
        uint32_t sb = base + (uint32_t)s * ST;
#pragma unroll
        for (int i = 0; i < 128 * CPR / 256; i++) {
            int idx = t + i * 256;
            int r = idx / CPR, c = idx % CPR;
            uint32_t so = r * PITCH + c * 16;
            cp_async16(sb + so, ah + (size_t)(row0 + r) * lda + kk + c * 8);
            if (NTERMS >= 2)
                cp_async16(sb + TILE + so, al + (size_t)(row0 + r) * lda + kk + c * 8);
            cp_async16(sb + WOFF + so, Wh + (size_t)(col0 + r) * ldw + k0 + c * 8);
            if (NTERMS == 3)
                cp_async16(sb + 3 * TILE + so, Wl + (size_t)(col0 + r) * ldw + k0 + c * 8);
        }
        cp_commit();
    };

    float acc[4][4][4];
#pragma unroll
    for (int a = 0; a < 4; a++)
#pragma unroll
        for (int b = 0; b < 4; b++)
#pragma unroll
            for (int c = 0; c < 4; c++) acc[a][b][c] = 0.f;

    // loop-invariant fragment row offsets
    uint32_t aoff[4], boff[2];
#pragma unroll
    for (int im = 0; im < 4; im++)
        aoff[im] = (uint32_t)(wm * 64 + im * 16 + (lane & 15)) * PITCH + (uint32_t)(lane >> 4) * 16;
#pragma unroll
    for (int ib = 0; ib < 2; ib++)
        boff[ib] = WOFF + (uint32_t)(wn * 32 + ib * 16 + ((lane & 16) ? 8 : 0) + (lane & 7)) * PITCH
                   + (uint32_t)((lane >> 3) & 1) * 16;

    int issued = 0;
    for (; issued < STAGES - 1 && issued < chunks; issued++)
        load_stage(issued % STAGES, issued);

    for (int i = 0; i < chunks; i++) {
        if (issued < chunks) { load_stage(issued % STAGES, issued); issued++; }
        int pend = chunks - 1 - i;
        if (pend > STAGES - 1) pend = STAGES - 1;
        if (pend == 0)      asm volatile("cp.async.wait_group 0;" ::: "memory");
        else if (pend == 1) asm volatile("cp.async.wait_group 1;" ::: "memory");
        else                asm volatile("cp.async.wait_group 2;" ::: "memory");
        __syncthreads();

        uint32_t sb = base + (uint32_t)(i % STAGES) * ST;

        if (NTERMS == 1) {
            // register double-buffered fragments; BK=64 -> 4 ks steps
            uint32_t ra2[2][4][4], rb2[2][2][4];
#pragma unroll
            for (int im = 0; im < 4; im++) ldmx4(ra2[0][im], sb + aoff[im]);
#pragma unroll
            for (int ib = 0; ib < 2; ib++) ldmx4(rb2[0][ib], sb + boff[ib]);
#pragma unroll
            for (int ks = 0; ks < 4; ks++) {
                const int cur = ks & 1, nxt = cur ^ 1;
                if (ks < 3) {
                    uint32_t adv = (uint32_t)(ks + 1) * 32;
#pragma unroll
                    for (int im = 0; im < 4; im++) ldmx4(ra2[nxt][im], sb + aoff[im] + adv);
#pragma unroll
                    for (int ib = 0; ib < 2; ib++) ldmx4(rb2[nxt][ib], sb + boff[ib] + adv);
                }
#pragma unroll
                for (int im = 0; im < 4; im++)
#pragma unroll
                    for (int in = 0; in < 4; in++)
                        mma16816(acc[im][in], ra2[cur][im],
                                 rb2[cur][in >> 1][(in & 1) * 2], rb2[cur][in >> 1][(in & 1) * 2 + 1]);
            }
        } else {
#pragma unroll
            for (int ks = 0; ks < BK / 16; ks++) {
                uint32_t adv = (uint32_t)ks * 32;
                uint32_t ra[4][4], rbh[2][4];
#pragma unroll
                for (int im = 0; im < 4; im++) ldmx4(ra[im], sb + aoff[im] + adv);
#pragma unroll
                for (int ib = 0; ib < 2; ib++) ldmx4(rbh[ib], sb + boff[ib] + adv);
#pragma unroll
                for (int im = 0; im < 4; im++)
#pragma unroll
                    for (int in = 0; in < 4; in++)
                        mma16816(acc[im][in], ra[im], rbh[in >> 1][(in & 1) * 2], rbh[in >> 1][(in & 1) * 2 + 1]);
                if (NTERMS == 3) {
                    uint32_t rbl[2][4];
#pragma unroll
                    for (int ib = 0; ib < 2; ib++) ldmx4(rbl[ib], sb + TILE + boff[ib] + adv);
#pragma unroll
                    for (int im = 0; im < 4; im++)
#pragma unroll
                        for (int in = 0; in < 4; in++)
                            mma16816(acc[im][in], ra[im], rbl[in >> 1][(in & 1) * 2], rbl[in >> 1][(in & 1) * 2 + 1]);
                }
                // A-lo * W-hi
#pragma unroll
                for (int im = 0; im < 4; im++)
                    ldmx4(ra[im], sb + TILE + aoff[im] + adv - WOFF + 2 * TILE);  // A-lo tile at +TILE
#pragma unroll
                for (int im = 0; im < 4; im++)
#pragma unroll
                    for (int in = 0; in < 4; in++)
                        mma16816(acc[im][in], ra[im], rbh[in >> 1][(in & 1) * 2], rbh[in >> 1][(in & 1) * 2 + 1]);
            }
        }
        __syncthreads();
    }

    // ---------------- epilogue ----------------
    if (OUTMODE == 4) {
        float* sred = (float*)sm;   // 128 rows x 5 outputs
        for (int idx = t; idx < 128 * OUTD; idx += 256) sred[idx] = 0.f;
        __syncthreads();
#pragma unroll
        for (int im = 0; im < 4; im++) {
            float pp0[OUTD], pp1[OUTD];
#pragma unroll
            for (int o = 0; o < OUTD; o++) { pp0[o] = 0.f; pp1[o] = 0.f; }
            int m = row0 + wm * 64 + im * 16 + (lane >> 2);
#pragma unroll
            for (int in = 0; in < 4; in++) {
                int c = col0 + wn * 32 + in * 8 + (lane & 3) * 2;
                float n00 = fmaxf(acc[im][in][0] + bg[512 + c], 0.f);
                float n01 = fmaxf(acc[im][in][1] + bg[512 + c + 1], 0.f);
                float n10 = fmaxf(acc[im][in][2] + bg[512 + c], 0.f);
                float n11 = fmaxf(acc[im][in][3] + bg[512 + c + 1], 0.f);
                float z00 = zbuf[(size_t)m * 256 + c], z01 = zbuf[(size_t)m * 256 + c + 1];
                float z10 = zbuf[(size_t)(m + 8) * 256 + c], z11 = zbuf[(size_t)(m + 8) * 256 + c + 1];
                float p00 = prevp[(size_t)m * 256 + c], p01 = prevp[(size_t)m * 256 + c + 1];
                float p10 = prevp[(size_t)(m + 8) * 256 + c], p11 = prevp[(size_t)(m + 8) * 256 + c + 1];
                float h00 = (1.f - z00) * n00 + z00 * p00;
                float h01 = (1.f - z01) * n01 + z01 * p01;
                float h10 = (1.f - z10) * n10 + z10 * p10;
                float h11 = (1.f - z11) * n11 + z11 * p11;
                outh[(size_t)m * 256 + c] = h00;
                outh[(size_t)m * 256 + c + 1] = h01;
                outh[(size_t)(m + 8) * 256 + c] = h10;
                outh[(size_t)(m + 8) * 256 + c + 1] = h11;
#pragma unroll
                for (int o = 0; o < OUTD; o++) {
                    float w0 = Wp[o * 256 + c], w1 = Wp[o * 256 + c + 1];
                    pp0[o] += h00 * w0 + h01 * w1;
                    pp1[o] += h10 * w0 + h11 * w1;
                }
            }
#pragma unroll
            for (int off = 1; off <= 2; off <<= 1)
#pragma unroll
                for (int o = 0; o < OUTD; o++) {
                    pp0[o] += __shfl_xor_sync(0xffffffffu, pp0[o], off);
                    pp1[o] += __shfl_xor_sync(0xffffffffu, pp1[o], off);
                }
            if ((lane & 3) == 0) {
                int r0 = wm * 64 + im * 16 + (lane >> 2);
#pragma unroll
                for (int o = 0; o < OUTD; o++) {
                    atomicAdd(&sred[r0 * OUTD + o], pp0[o]);
                    atomicAdd(&sred[(r0 + 8) * OUTD + o], pp1[o]);
                }
            }
        }
        __syncthreads();
        for (int idx = t; idx < 128 * OUTD; idx += 256)
            atomicAdd(&predout[(size_t)(row0 + idx / OUTD) * OUTD + idx % OUTD], sred[idx]);
        return;
    }

    auto emit = [&](int mm, int cc, float v) {
        if (OUTMODE == 2) {
            Cout[(size_t)mm * ldc + coff + cc] = __float2half_rn(fmaxf(v, 0.f));
        } else if (OUTMODE == 3) {
            float s = 1.f / (1.f + expf(-(v + bg[cc])));
            if (cc < 256) {
                zbuf[(size_t)mm * 256 + cc] = s;
            } else {
                int j = cc - 256;
                rhout[(size_t)mm * 256 + j] = __float2half_rn(s * prevp[(size_t)mm * 256 + j]);
            }
        } else {  // 5: fp32 + bias
            outh[(size_t)mm * 256 + cc] = v + bg[cc];
        }
    };
#pragma unroll
    for (int im = 0; im < 4; im++) {
#pragma unroll
        for (int in = 0; in < 4; in++) {
            int m = row0 + wm * 64 + im * 16 + (lane >> 2);
            int c = col0 + wn * 32 + in * 8 + (lane & 3) * 2;
            emit(m, c, acc[im][in][0]);
            emit(m, c + 1, acc[im][in][1]);
            emit(m + 8, c, acc[im][in][2]);
            emit(m + 8, c + 1, acc[im][in][3]);
        }
    }
}

// ---------------- weight merge + convert + Mt/cvec (fused) ----------------
__global__ void merge_weights(
    const float* __restrict__ Whe, const float* __restrict__ Wih, const float* __restrict__ Whh,
    const float* __restrict__ Wt, const float* __restrict__ Ws, const float* __restrict__ bt,
    fp16* __restrict__ WheO,
    fp16* __restrict__ Uzr, fp16* __restrict__ Un,
    fp16* __restrict__ MtH, fp16* __restrict__ MtL, float* __restrict__ cvec)
{
    int b = blockIdx.x;
    if (b >= 2816) {
        // computeM part: blocks 2816..3071 -> k = b - 2816
        int k = b - 2816, j = threadIdx.x;
        float s = 0.f;
#pragma unroll 8
        for (int a = 0; a < 64; a++) s = fmaf(Wt[a * 256 + k], Ws[a * 256 + j], s);
        split_write(MtH, MtL, (size_t)j * 256 + k, s);
        if (k == 0) {
            float c = 0.f;
#pragma unroll 8
            for (int a = 0; a < 64; a++) c = fmaf(bt[a], Ws[a * 256 + j], c);
            cvec[j] = c;
        }
        return;
    }
    int i = b * 256 + threadIdx.x;
    if (i < 131072) {
        WheO[i] = __float2half_rn(Whe[i]);
    } else if (i < 131072 + 393216) {
        int q = i - 131072;
        int j = q / 768, k = q - j * 768;
        int g = j >> 8, r = j & 255;
        float x = (k < 512) ? Wih[g * 131072 + r * 512 + k] : Whh[g * 65536 + r * 256 + (k - 512)];
        Uzr[q] = __float2half_rn(x);
    } else {
        int q = i - 524288;
        int j = q / 768, k = q - j * 768;
        float x = (k < 512) ? Wih[262144 + j * 512 + k] : Whh[131072 + j * 256 + (k - 512)];
        Un[q] = __float2half_rn(x);
    }
}

// ---------------- attention (writes in1 hi, cols 256:512) ----------------
__global__ void __launch_bounds__(256) attn_kernel(
    const float* __restrict__ spat, const float* __restrict__ V,
    fp16* __restrict__ hi)
{
    __shared__ float sp[NE * NH];
    __shared__ float vs[NH];
    __shared__ float attn_s[NE];
    __shared__ float ws[NE];

    int n = blockIdx.x;
    int t = threadIdx.x;

    vs[t] = V[(size_t)n * NH + t];
    const float4* g = (const float4*)(spat + (size_t)n * NE * NH);
    float4* s4 = (float4*)sp;
#pragma unroll
    for (int i = 0; i < 8; i++) s4[t + i * 256] = g[t + i * 256];
    __syncthreads();

    int warp = t >> 5, lane = t & 31;
#pragma unroll
    for (int ei = 0; ei < 4; ei++) {
        int e = warp * 4 + ei;
        float s = 0.f;
#pragma unroll
        for (int i = 0; i < 8; i++)
            s = fmaf(sp[e * NH + lane + i * 32], vs[lane + i * 32], s);
#pragma unroll
        for (int o = 16; o; o >>= 1) s += __shfl_xor_sync(0xffffffffu, s, o);
        if (lane == 0) attn_s[e] = s * 4.0f;
    }
    __syncthreads();

    if (t < 32) {
        float a = attn_s[t];
        float m = a;
#pragma unroll
        for (int o = 16; o; o >>= 1) m = fmaxf(m, __shfl_xor_sync(0xffffffffu, m, o));
        float p = expf(a - m);
        float ssum = p;
#pragma unroll
        for (int o = 16; o; o >>= 1) ssum += __shfl_xor_sync(0xffffffffu, ssum, o);
        ws[t] = p / ssum;
    }
    __syncthreads();

    float acc = 0.f;
#pragma unroll
    for (int e = 0; e < NE; e++) acc = fmaf(ws[e], sp[e * NH + t], acc);
    hi[(size_t)n * 512 + 256 + t] = __float2half_rn(acc);
}

// ---------------- fused prep: prev fp16, th split, x_e, pred-bias init ----------
__global__ void __launch_bounds__(256) prep_kernel(
    const float* __restrict__ prev, const float* __restrict__ th,
    const float* __restrict__ xy, const float* __restrict__ Wxy,
    const float* __restrict__ bp,
    fp16* __restrict__ ph,
    fp16* __restrict__ i1h, fp16* __restrict__ i1l,
    fp16* __restrict__ ch, float* __restrict__ predout)
{
    int n = blockIdx.x, c = threadIdx.x;
    size_t i = (size_t)n * 256 + c;
    ph[i] = __float2half_rn(prev[i]);
    split_write(i1h, i1l, (size_t)n * 512 + c, th[i]);
    float x0 = xy[n * 2 + 0], x1 = xy[n * 2 + 1];
    float2 w = *(const float2*)&Wxy[c * 2];
    float v = fmaxf(fmaf(x0, w.x, x1 * w.y), 0.f);
    ch[(size_t)n * 512 + c] = __float2half_rn(v);
    if (c < OUTD) predout[(size_t)n * OUTD + c] = bp[c];
}

// ---------------- host launcher ----------------
extern "C" void kernel_launch(void* const* d_in, const int* in_sizes, int n_in,
                              void* d_out, int out_size)
{
    const float* xy   = (const float*)d_in[0];
    const float* th   = (const float*)d_in[1];
    const float* spat = (const float*)d_in[2];
    const float* prev = (const float*)d_in[3];
    const float* Wt   = (const float*)d_in[4];
    const float* bt   = (const float*)d_in[5];
    const float* Ws   = (const float*)d_in[6];
    // d_in[7] = bs: softmax-invariant, dropped.
    const float* Wxy  = (const float*)d_in[8];
    const float* Whe  = (const float*)d_in[9];
    const float* Wih  = (const float*)d_in[10];
    const float* Whh  = (const float*)d_in[11];
    const float* bg   = (const float*)d_in[12];
    const float* Wp   = (const float*)d_in[13];
    const float* bp   = (const float*)d_in[14];

    float* out_pred   = (float*)d_out;
    float* out_hidden = (float*)d_out + NN * OUTD;

    float *pCvec, *pV, *pZ;
    fp16 *pMth, *pMtl, *pIn1h, *pIn1l, *pCat, *pPrev, *pRh;
    fp16 *pWhe, *pUzr, *pUn;
    cudaGetSymbolAddress((void**)&pCvec, g_cvec);
    cudaGetSymbolAddress((void**)&pV, g_V);
    cudaGetSymbolAddress((void**)&pZ, g_z);
    cudaGetSymbolAddress((void**)&pMth, g_Mt_hi);
    cudaGetSymbolAddress((void**)&pMtl, g_Mt_lo);
    cudaGetSymbolAddress((void**)&pIn1h, g_in1_hi);
    cudaGetSymbolAddress((void**)&pIn1l, g_in1_lo);
    cudaGetSymbolAddress((void**)&pCat, g_cat);
    cudaGetSymbolAddress((void**)&pPrev, g_prev);
    cudaGetSymbolAddress((void**)&pRh, g_rh);
    cudaGetSymbolAddress((void**)&pWhe, g_Whe);
    cudaGetSymbolAddress((void**)&pUzr, g_Uzr);
    cudaGetSymbolAddress((void**)&pUn, g_Un);

    const int SM3 = 2 * 4 * (128 * 80);    // 3-term BK32: 2 stages x 40960
    const int SM1 = 3 * 2 * (128 * 144);   // 1-term BK64: 3 stages x 36864
    cudaFuncSetAttribute((const void*)mma3<5, 3>, cudaFuncAttributeMaxDynamicSharedMemorySize, SM3);
    cudaFuncSetAttribute((const void*)mma3<2, 1>, cudaFuncAttributeMaxDynamicSharedMemorySize, SM1);
    cudaFuncSetAttribute((const void*)mma3<3, 1>, cudaFuncAttributeMaxDynamicSharedMemorySize, SM1);
    cudaFuncSetAttribute((const void*)mma3<4, 1>, cudaFuncAttributeMaxDynamicSharedMemorySize, SM1);

    dim3 blk(256);
    const int MB = NN / 128;

    // prep (merge_weights also computes Mt/cvec in its tail blocks)
    merge_weights<<<3072, blk>>>(Whe, Wih, Whh, Wt, Ws, bt,
                                 pWhe, pUzr, pUn, pMth, pMtl, pCvec);
    prep_kernel<<<NN, blk>>>(prev, th, xy, Wxy, bp, pPrev, pIn1h, pIn1l, pCat, out_pred);

    // V = th @ Mt^T + cvec (3-term, fp32 out)
    mma3<5, 3><<<dim3(2, MB), blk, SM3>>>(
        pIn1h, pIn1l, 512, pIn1h, pIn1l, 512, 1024,
        pMth, pMtl, 256, 256,
        nullptr, 0, 0, pCvec, nullptr, nullptr, nullptr, pV, nullptr, nullptr);

    // attention -> Hagg (in1 hi, cols 256:512)
    attn_kernel<<<NN, blk>>>(spat, pV, pIn1h);

    // H_e = relu(in1 @ Whe^T) -> cat[:,256:512]  (1-term, BK64, frag-dbuf)
    mma3<2, 1><<<dim3(2, MB), blk, SM1>>>(
        pIn1h, nullptr, 512, pIn1h, nullptr, 512, 512,
        pWhe, nullptr, 512, 512,
        pCat, 512, 256, nullptr, nullptr, nullptr, nullptr, nullptr, nullptr, nullptr);

    // z,r = sigmoid([cat||prev] @ Uzr^T + bg)  (1-term, BK64, frag-dbuf)
    mma3<3, 1><<<dim3(4, MB), blk, SM1>>>(
        pCat, nullptr, 512, pPrev, nullptr, 256, 512,
        pUzr, nullptr, 768, 768,
        nullptr, 0, 0, bg, prev, pZ, pRh, nullptr, nullptr, nullptr);

    // n GEMM + hidden + fused predict  (1-term, BK64, frag-dbuf)
    mma3<4, 1><<<dim3(2, MB), blk, SM1>>>(
        pCat, nullptr, 512, pRh, nullptr, 256, 512,
        pUn, nullptr, 768, 768,
        nullptr, 0, 0, bg, prev, pZ, nullptr, out_hidden, Wp, out_pred);
}

// round 14
// speedup vs baseline: 1.0683x; 1.0683x over previous
#include <cuda_runtime.h>
#include <cuda_fp16.h>
#include <math.h>
#include <stdint.h>

#define NN 16384
#define NE 32
#define NH 256
#define OUTD 5
#define ATTN_CTAS 444

typedef __half fp16;

// ---------------- scratch (device globals) ----------------
__device__ __align__(16) float g_cvec[256];
__device__ __align__(16) float g_V[NN * NH];
__device__ __align__(16) float g_z[NN * NH];

__device__ __align__(16) fp16 g_Mt_hi[256 * 256], g_Mt_lo[256 * 256];
__device__ __align__(16) fp16 g_in1_hi[NN * 512], g_in1_lo[NN * 512];  // [th || Hagg]
__device__ __align__(16) fp16 g_cat[NN * 512];                          // [x_e || H_e]
__device__ __align__(16) fp16 g_prev[NN * 256];
__device__ __align__(16) fp16 g_rh[NN * 256];
__device__ __align__(16) fp16 g_Whe[256 * 512];
__device__ __align__(16) fp16 g_Uzr[512 * 768];
__device__ __align__(16) fp16 g_Un[256 * 768];

// ---------------- PTX helpers ----------------
__device__ __forceinline__ uint32_t smem_u32(const void* p) {
    uint32_t a;
    asm("{ .reg .u64 t; cvta.to.shared.u64 t, %1; cvt.u32.u64 %0, t; }" : "=r"(a) : "l"(p));
    return a;
}
__device__ __forceinline__ void cp_async16(uint32_t s, const void* g) {
    asm volatile("cp.async.cg.shared.global [%0], [%1], 16;" :: "r"(s), "l"(g) : "memory");
}
__device__ __forceinline__ void cp_commit() {
    asm volatile("cp.async.commit_group;" ::: "memory");
}
__device__ __forceinline__ void ldmx4(uint32_t* r, uint32_t addr) {
    asm volatile("ldmatrix.sync.aligned.m8n8.x4.shared.b16 {%0,%1,%2,%3}, [%4];"
                 : "=r"(r[0]), "=r"(r[1]), "=r"(r[2]), "=r"(r[3]) : "r"(addr));
}
__device__ __forceinline__ void mma16816(float* c, const uint32_t* a, uint32_t b0, uint32_t b1) {
    asm volatile(
        "mma.sync.aligned.m16n8k16.row.col.f32.f16.f16.f32 "
        "{%0,%1,%2,%3}, {%4,%5,%6,%7}, {%8,%9}, {%0,%1,%2,%3};"
        : "+f"(c[0]), "+f"(c[1]), "+f"(c[2]), "+f"(c[3])
        : "r"(a[0]), "r"(a[1]), "r"(a[2]), "r"(a[3]), "r"(b0), "r"(b1));
}
__device__ __forceinline__ void split_write(fp16* hi, fp16* lo, size_t off, float x) {
    fp16 h = __float2half_rn(x);
    hi[off] = h;
    lo[off] = __float2half_rn(x - __half2float(h));
}

// ---------------- fp16 split GEMM: BM=BN=128, 256 thr, 2 CTA/SM ----------
// NTERMS=3: BK=32, A(hi,lo) x W(hi,lo), 2-stage (40KB/stage), pitch 80.
// NTERMS=1: BK=64, A x W single, 3-stage (36.9KB/stage), pitch 144, frag dbuf.
// OUTMODE: 2 = relu + fp16; 3 = zr epilogue; 4 = n/final + fused predict; 5 = fp32+bias.
template <int OUTMODE, int NTERMS>
__global__ void __launch_bounds__(256, 2) mma3(
    const fp16* __restrict__ A1h, const fp16* __restrict__ A1l, int lda1,
    const fp16* __restrict__ A2h, const fp16* __restrict__ A2l, int lda2, int splitK,
    const fp16* __restrict__ Wh, const fp16* __restrict__ Wl, int ldw, int K,
    fp16* __restrict__ Cout, int ldc, int coff,
    const float* __restrict__ bg, const float* __restrict__ prevp,
    float* __restrict__ zbuf,
    fp16* __restrict__ rhout,
    float* __restrict__ outh,
    const float* __restrict__ Wp, float* __restrict__ predout)
{
    constexpr int BK = (NTERMS == 1) ? 64 : 32;
    constexpr uint32_t PITCH = (NTERMS == 1) ? 144u : 80u;
    constexpr uint32_t TILE = 128u * PITCH;
    constexpr uint32_t ST = (NTERMS == 3) ? 4 * TILE : TILE * 2;
    constexpr int STAGES = (NTERMS == 3) ? 2 : 3;
    constexpr int CPR = BK / 8;
    constexpr uint32_t WOFF = (NTERMS == 1) ? TILE : 2 * TILE;
    extern __shared__ char sm[];
    const uint32_t base = smem_u32(sm);
    const int t = threadIdx.x, wid = t >> 5, lane = t & 31;
    const int wm = wid & 1, wn = wid >> 1;
    const int row0 = blockIdx.y * 128, col0 = blockIdx.x * 128;
    const int chunks = K / BK;

    auto load_stage = [&](int s, int ck) {
        int k0 = ck * BK;
        const fp16 *ah, *al;
        int lda, kk;
        if (k0 < splitK) { ah = A1h; al = A1l; lda = lda1; kk = k0; }
        else             { ah = A2h; al = A2l; lda = lda2; kk = k0 - splitK; }
        uint32_t sb = base + (uint32_t)s * ST;
#pragma unroll
        for (int i = 0; i < 128 * CPR / 256; i++) {
            int idx = t + i * 256;
            int r = idx / CPR, c = idx % CPR;
            uint32_t so = r * PITCH + c * 16;
            cp_async16(sb + so, ah + (size_t)(row0 + r) * lda + kk + c * 8);
            if (NTERMS >= 2)
                cp_async16(sb + TILE + so, al + (size_t)(row0 + r) * lda + kk + c * 8);
            cp_async16(sb + WOFF + so, Wh + (size_t)(col0 + r) * ldw + k0 + c * 8);
            if (NTERMS == 3)
                cp_async16(sb + 3 * TILE + so, Wl + (size_t)(col0 + r) * ldw + k0 + c * 8);
        }
        cp_commit();
    };

    float acc[4][4][4];
#pragma unroll
    for (int a = 0; a < 4; a++)
#pragma unroll
        for (int b = 0; b < 4; b++)
#pragma unroll
            for (int c = 0; c < 4; c++) acc[a][b][c] = 0.f;

    uint32_t aoff[4], boff[2];
#pragma unroll
    for (int im = 0; im < 4; im++)
        aoff[im] = (uint32_t)(wm * 64 + im * 16 + (lane & 15)) * PITCH + (uint32_t)(lane >> 4) * 16;
#pragma unroll
    for (int ib = 0; ib < 2; ib++)
        boff[ib] = WOFF + (uint32_t)(wn * 32 + ib * 16 + ((lane & 16) ? 8 : 0) + (lane & 7)) * PITCH
                   + (uint32_t)((lane >> 3) & 1) * 16;

    int issued = 0;
    for (; issued < STAGES - 1 && issued < chunks; issued++)
        load_stage(issued % STAGES, issued);

    for (int i = 0; i < chunks; i++) {
        if (issued < chunks) { load_stage(issued % STAGES, issued); issued++; }
        int pend = chunks - 1 - i;
        if (pend > STAGES - 1) pend = STAGES - 1;
        if (pend == 0)      asm volatile("cp.async.wait_group 0;" ::: "memory");
        else if (pend == 1) asm volatile("cp.async.wait_group 1;" ::: "memory");
        else                asm volatile("cp.async.wait_group 2;" ::: "memory");
        __syncthreads();

        uint32_t sb = base + (uint32_t)(i % STAGES) * ST;

        if (NTERMS == 1) {
            uint32_t ra2[2][4][4], rb2[2][2][4];
#pragma unroll
            for (int im = 0; im < 4; im++) ldmx4(ra2[0][im], sb + aoff[im]);
#pragma unroll
            for (int ib = 0; ib < 2; ib++) ldmx4(rb2[0][ib], sb + boff[ib]);
#pragma unroll
            for (int ks = 0; ks < 4; ks++) {
                const int cur = ks & 1, nxt = cur ^ 1;
                if (ks < 3) {
                    uint32_t adv = (uint32_t)(ks + 1) * 32;
#pragma unroll
                    for (int im = 0; im < 4; im++) ldmx4(ra2[nxt][im], sb + aoff[im] + adv);
#pragma unroll
                    for (int ib = 0; ib < 2; ib++) ldmx4(rb2[nxt][ib], sb + boff[ib] + adv);
                }
#pragma unroll
                for (int im = 0; im < 4; im++)
#pragma unroll
                    for (int in = 0; in < 4; in++)
                        mma16816(acc[im][in], ra2[cur][im],
                                 rb2[cur][in >> 1][(in & 1) * 2], rb2[cur][in >> 1][(in & 1) * 2 + 1]);
            }
        } else {
#pragma unroll
            for (int ks = 0; ks < BK / 16; ks++) {
                uint32_t adv = (uint32_t)ks * 32;
                uint32_t ra[4][4], rbh[2][4];
#pragma unroll
                for (int im = 0; im < 4; im++) ldmx4(ra[im], sb + aoff[im] + adv);
#pragma unroll
                for (int ib = 0; ib < 2; ib++) ldmx4(rbh[ib], sb + boff[ib] + adv);
#pragma unroll
                for (int im = 0; im < 4; im++)
#pragma unroll
                    for (int in = 0; in < 4; in++)
                        mma16816(acc[im][in], ra[im], rbh[in >> 1][(in & 1) * 2], rbh[in >> 1][(in & 1) * 2 + 1]);
                if (NTERMS == 3) {
                    uint32_t rbl[2][4];
#pragma unroll
                    for (int ib = 0; ib < 2; ib++) ldmx4(rbl[ib], sb + TILE + boff[ib] + adv);
#pragma unroll
                    for (int im = 0; im < 4; im++)
#pragma unroll
                        for (int in = 0; in < 4; in++)
                            mma16816(acc[im][in], ra[im], rbl[in >> 1][(in & 1) * 2], rbl[in >> 1][(in & 1) * 2 + 1]);
                }
#pragma unroll
                for (int im = 0; im < 4; im++)
                    ldmx4(ra[im], sb + TILE + aoff[im] + adv - WOFF + 2 * TILE);
#pragma unroll
                for (int im = 0; im < 4; im++)
#pragma unroll
                    for (int in = 0; in < 4; in++)
                        mma16816(acc[im][in], ra[im], rbh[in >> 1][(in & 1) * 2], rbh[in >> 1][(in & 1) * 2 + 1]);
            }
        }
        __syncthreads();
    }

    // ---------------- epilogue ----------------
    if (OUTMODE == 4) {
        float* sred = (float*)sm;
        for (int idx = t; idx < 128 * OUTD; idx += 256) sred[idx] = 0.f;
        __syncthreads();
#pragma unroll
        for (int im = 0; im < 4; im++) {
            float pp0[OUTD], pp1[OUTD];
#pragma unroll
            for (int o = 0; o < OUTD; o++) { pp0[o] = 0.f; pp1[o] = 0.f; }
            int m = row0 + wm * 64 + im * 16 + (lane >> 2);
#pragma unroll
            for (int in = 0; in < 4; in++) {
                int c = col0 + wn * 32 + in * 8 + (lane & 3) * 2;
                float n00 = fmaxf(acc[im][in][0] + bg[512 + c], 0.f);
                float n01 = fmaxf(acc[im][in][1] + bg[512 + c + 1], 0.f);
                float n10 = fmaxf(acc[im][in][2] + bg[512 + c], 0.f);
                float n11 = fmaxf(acc[im][in][3] + bg[512 + c + 1], 0.f);
                float z00 = zbuf[(size_t)m * 256 + c], z01 = zbuf[(size_t)m * 256 + c + 1];
                float z10 = zbuf[(size_t)(m + 8) * 256 + c], z11 = zbuf[(size_t)(m + 8) * 256 + c + 1];
                float p00 = prevp[(size_t)m * 256 + c], p01 = prevp[(size_t)m * 256 + c + 1];
                float p10 = prevp[(size_t)(m + 8) * 256 + c], p11 = prevp[(size_t)(m + 8) * 256 + c + 1];
                float h00 = (1.f - z00) * n00 + z00 * p00;
                float h01 = (1.f - z01) * n01 + z01 * p01;
                float h10 = (1.f - z10) * n10 + z10 * p10;
                float h11 = (1.f - z11) * n11 + z11 * p11;
                outh[(size_t)m * 256 + c] = h00;
                outh[(size_t)m * 256 + c + 1] = h01;
                outh[(size_t)(m + 8) * 256 + c] = h10;
                outh[(size_t)(m + 8) * 256 + c + 1] = h11;
#pragma unroll
                for (int o = 0; o < OUTD; o++) {
                    float w0 = Wp[o * 256 + c], w1 = Wp[o * 256 + c + 1];
                    pp0[o] += h00 * w0 + h01 * w1;
                    pp1[o] += h10 * w0 + h11 * w1;
                }
            }
#pragma unroll
            for (int off = 1; off <= 2; off <<= 1)
#pragma unroll
                for (int o = 0; o < OUTD; o++) {
                    pp0[o] += __shfl_xor_sync(0xffffffffu, pp0[o], off);
                    pp1[o] += __shfl_xor_sync(0xffffffffu, pp1[o], off);
                }
            if ((lane & 3) == 0) {
                int r0 = wm * 64 + im * 16 + (lane >> 2);
#pragma unroll
                for (int o = 0; o < OUTD; o++) {
                    atomicAdd(&sred[r0 * OUTD + o], pp0[o]);
                    atomicAdd(&sred[(r0 + 8) * OUTD + o], pp1[o]);
                }
            }
        }
        __syncthreads();
        for (int idx = t; idx < 128 * OUTD; idx += 256)
            atomicAdd(&predout[(size_t)(row0 + idx / OUTD) * OUTD + idx % OUTD], sred[idx]);
        return;
    }

    auto emit = [&](int mm, int cc, float v) {
        if (OUTMODE == 2) {
            Cout[(size_t)mm * ldc + coff + cc] = __float2half_rn(fmaxf(v, 0.f));
        } else if (OUTMODE == 3) {
            float s = 1.f / (1.f + expf(-(v + bg[cc])));
            if (cc < 256) {
                zbuf[(size_t)mm * 256 + cc] = s;
            } else {
                int j = cc - 256;
                rhout[(size_t)mm * 256 + j] = __float2half_rn(s * prevp[(size_t)mm * 256 + j]);
            }
        } else {
            outh[(size_t)mm * 256 + cc] = v + bg[cc];
        }
    };
#pragma unroll
    for (int im = 0; im < 4; im++) {
#pragma unroll
        for (int in = 0; in < 4; in++) {
            int m = row0 + wm * 64 + im * 16 + (lane >> 2);
            int c = col0 + wn * 32 + in * 8 + (lane & 3) * 2;
            emit(m, c, acc[im][in][0]);
            emit(m, c + 1, acc[im][in][1]);
            emit(m + 8, c, acc[im][in][2]);
            emit(m + 8, c + 1, acc[im][in][3]);
        }
    }
}

// ---------------- weight merge + convert + Mt/cvec (fused) ----------------
__global__ void merge_weights(
    const float* __restrict__ Whe, const float* __restrict__ Wih, const float* __restrict__ Whh,
    const float* __restrict__ Wt, const float* __restrict__ Ws, const float* __restrict__ bt,
    fp16* __restrict__ WheO,
    fp16* __restrict__ Uzr, fp16* __restrict__ Un,
    fp16* __restrict__ MtH, fp16* __restrict__ MtL, float* __restrict__ cvec)
{
    int b = blockIdx.x;
    if (b >= 2816) {
        int k = b - 2816, j = threadIdx.x;
        float s = 0.f;
#pragma unroll 8
        for (int a = 0; a < 64; a++) s = fmaf(Wt[a * 256 + k], Ws[a * 256 + j], s);
        split_write(MtH, MtL, (size_t)j * 256 + k, s);
        if (k == 0) {
            float c = 0.f;
#pragma unroll 8
            for (int a = 0; a < 64; a++) c = fmaf(bt[a], Ws[a * 256 + j], c);
            cvec[j] = c;
        }
        return;
    }
    int i = b * 256 + threadIdx.x;
    if (i < 131072) {
        WheO[i] = __float2half_rn(Whe[i]);
    } else if (i < 131072 + 393216) {
        int q = i - 131072;
        int j = q / 768, k = q - j * 768;
        int g = j >> 8, r = j & 255;
        float x = (k < 512) ? Wih[g * 131072 + r * 512 + k] : Whh[g * 65536 + r * 256 + (k - 512)];
        Uzr[q] = __float2half_rn(x);
    } else {
        int q = i - 524288;
        int j = q / 768, k = q - j * 768;
        float x = (k < 512) ? Wih[262144 + j * 512 + k] : Whh[131072 + j * 256 + (k - 512)];
        Un[q] = __float2half_rn(x);
    }
}

// ---------------- persistent double-buffered attention ----------------
// Each CTA strides over nodes, prefetching node+ATTN_CTAS's 32KB spat tile + V
// via cp.async while computing the current node. Steady-state = pure HBM stream.
#define ATTN_SMEM (2 * (NE * NH * 4 + NH * 4) + 512)

__global__ void __launch_bounds__(256, 3) attn_kernel(
    const float* __restrict__ spat, const float* __restrict__ V,
    fp16* __restrict__ hi)
{
    extern __shared__ char asm_raw[];
    float* sp = (float*)asm_raw;                  // [2][NE*NH]
    float* vs = (float*)(asm_raw + 2 * NE * NH * 4);  // [2][NH]
    float* attn_s = (float*)(asm_raw + 2 * (NE * NH * 4 + NH * 4));        // [NE]
    float* ws = attn_s + NE;                                               // [NE]
    const uint32_t sp_u = smem_u32(sp);
    const uint32_t vs_u = smem_u32(vs);

    int t = threadIdx.x;
    int warp = t >> 5, lane = t & 31;

    auto load_node = [&](int buf, int n) {
        uint32_t spb = sp_u + (uint32_t)buf * (NE * NH * 4);
#pragma unroll
        for (int i = 0; i < 8; i++) {
            int idx = t + i * 256;   // [0,2048) float4 chunks
            cp_async16(spb + idx * 16, spat + (size_t)n * NE * NH + idx * 4);
        }
        if (t < 64)
            cp_async16(vs_u + (uint32_t)buf * (NH * 4) + t * 16, V + (size_t)n * NH + t * 4);
        cp_commit();
    };

    int node = blockIdx.x;
    if (node >= NN) return;
    load_node(0, node);
    int buf = 0;

    for (; node < NN; node += ATTN_CTAS) {
        int next = node + ATTN_CTAS;
        bool pre = (next < NN);
        if (pre) load_node(buf ^ 1, next);

        if (pre) asm volatile("cp.async.wait_group 1;" ::: "memory");
        else     asm volatile("cp.async.wait_group 0;" ::: "memory");
        __syncthreads();

        float* spc = sp + buf * (NE * NH);
        float* vsc = vs + buf * NH;

        // dots: each warp handles 4 edges
#pragma unroll
        for (int ei = 0; ei < 4; ei++) {
            int e = warp * 4 + ei;
            float s = 0.f;
#pragma unroll
            for (int i = 0; i < 8; i++)
                s = fmaf(spc[e * NH + lane + i * 32], vsc[lane + i * 32], s);
#pragma unroll
            for (int o = 16; o; o >>= 1) s += __shfl_xor_sync(0xffffffffu, s, o);
            if (lane == 0) attn_s[e] = s * 4.0f;   // temperature = E/sqrt(A)
        }
        __syncthreads();

        if (t < 32) {
            float a = attn_s[t];
            float m = a;
#pragma unroll
            for (int o = 16; o; o >>= 1) m = fmaxf(m, __shfl_xor_sync(0xffffffffu, m, o));
            float p = expf(a - m);
            float ssum = p;
#pragma unroll
            for (int o = 16; o; o >>= 1) ssum += __shfl_xor_sync(0xffffffffu, ssum, o);
            ws[t] = p / ssum;
        }
        __syncthreads();

        float acc = 0.f;
#pragma unroll
        for (int e = 0; e < NE; e++) acc = fmaf(ws[e], spc[e * NH + t], acc);
        hi[(size_t)node * 512 + 256 + t] = __float2half_rn(acc);

        __syncthreads();   // all reads of this buffer done before it is prefetch target
        buf ^= 1;
    }
}

// ---------------- fused prep: prev fp16, th split, x_e, pred-bias init ----------
__global__ void __launch_bounds__(256) prep_kernel(
    const float* __restrict__ prev, const float* __restrict__ th,
    const float* __restrict__ xy, const float* __restrict__ Wxy,
    const float* __restrict__ bp,
    fp16* __restrict__ ph,
    fp16* __restrict__ i1h, fp16* __restrict__ i1l,
    fp16* __restrict__ ch, float* __restrict__ predout)
{
    int n = blockIdx.x, c = threadIdx.x;
    size_t i = (size_t)n * 256 + c;
    ph[i] = __float2half_rn(prev[i]);
    split_write(i1h, i1l, (size_t)n * 512 + c, th[i]);
    float x0 = xy[n * 2 + 0], x1 = xy[n * 2 + 1];
    float2 w = *(const float2*)&Wxy[c * 2];
    float v = fmaxf(fmaf(x0, w.x, x1 * w.y), 0.f);
    ch[(size_t)n * 512 + c] = __float2half_rn(v);
    if (c < OUTD) predout[(size_t)n * OUTD + c] = bp[c];
}

// ---------------- host launcher ----------------
extern "C" void kernel_launch(void* const* d_in, const int* in_sizes, int n_in,
                              void* d_out, int out_size)
{
    const float* xy   = (const float*)d_in[0];
    const float* th   = (const float*)d_in[1];
    const float* spat = (const float*)d_in[2];
    const float* prev = (const float*)d_in[3];
    const float* Wt   = (const float*)d_in[4];
    const float* bt   = (const float*)d_in[5];
    const float* Ws   = (const float*)d_in[6];
    // d_in[7] = bs: softmax-invariant, dropped.
    const float* Wxy  = (const float*)d_in[8];
    const float* Whe  = (const float*)d_in[9];
    const float* Wih  = (const float*)d_in[10];
    const float* Whh  = (const float*)d_in[11];
    const float* bg   = (const float*)d_in[12];
    const float* Wp   = (const float*)d_in[13];
    const float* bp   = (const float*)d_in[14];

    float* out_pred   = (float*)d_out;
    float* out_hidden = (float*)d_out + NN * OUTD;

    float *pCvec, *pV, *pZ;
    fp16 *pMth, *pMtl, *pIn1h, *pIn1l, *pCat, *pPrev, *pRh;
    fp16 *pWhe, *pUzr, *pUn;
    cudaGetSymbolAddress((void**)&pCvec, g_cvec);
    cudaGetSymbolAddress((void**)&pV, g_V);
    cudaGetSymbolAddress((void**)&pZ, g_z);
    cudaGetSymbolAddress((void**)&pMth, g_Mt_hi);
    cudaGetSymbolAddress((void**)&pMtl, g_Mt_lo);
    cudaGetSymbolAddress((void**)&pIn1h, g_in1_hi);
    cudaGetSymbolAddress((void**)&pIn1l, g_in1_lo);
    cudaGetSymbolAddress((void**)&pCat, g_cat);
    cudaGetSymbolAddress((void**)&pPrev, g_prev);
    cudaGetSymbolAddress((void**)&pRh, g_rh);
    cudaGetSymbolAddress((void**)&pWhe, g_Whe);
    cudaGetSymbolAddress((void**)&pUzr, g_Uzr);
    cudaGetSymbolAddress((void**)&pUn, g_Un);

    const int SM3 = 2 * 4 * (128 * 80);
    const int SM1 = 3 * 2 * (128 * 144);
    cudaFuncSetAttribute((const void*)mma3<5, 3>, cudaFuncAttributeMaxDynamicSharedMemorySize, SM3);
    cudaFuncSetAttribute((const void*)mma3<2, 1>, cudaFuncAttributeMaxDynamicSharedMemorySize, SM1);
    cudaFuncSetAttribute((const void*)mma3<3, 1>, cudaFuncAttributeMaxDynamicSharedMemorySize, SM1);
    cudaFuncSetAttribute((const void*)mma3<4, 1>, cudaFuncAttributeMaxDynamicSharedMemorySize, SM1);
    cudaFuncSetAttribute((const void*)attn_kernel, cudaFuncAttributeMaxDynamicSharedMemorySize, ATTN_SMEM);

    dim3 blk(256);
    const int MB = NN / 128;

    // prep
    merge_weights<<<3072, blk>>>(Whe, Wih, Whh, Wt, Ws, bt,
                                 pWhe, pUzr, pUn, pMth, pMtl, pCvec);
    prep_kernel<<<NN, blk>>>(prev, th, xy, Wxy, bp, pPrev, pIn1h, pIn1l, pCat, out_pred);

    // V = th @ Mt^T + cvec (3-term, fp32 out)
    mma3<5, 3><<<dim3(2, MB), blk, SM3>>>(
        pIn1h, pIn1l, 512, pIn1h, pIn1l, 512, 1024,
        pMth, pMtl, 256, 256,
        nullptr, 0, 0, pCvec, nullptr, nullptr, nullptr, pV, nullptr, nullptr);

    // attention -> Hagg (persistent, double-buffered)
    attn_kernel<<<ATTN_CTAS, blk, ATTN_SMEM>>>(spat, pV, pIn1h);

    // H_e = relu(in1 @ Whe^T) -> cat[:,256:512]  (1-term, BK64)
    mma3<2, 1><<<dim3(2, MB), blk, SM1>>>(
        pIn1h, nullptr, 512, pIn1h, nullptr, 512, 512,
        pWhe, nullptr, 512, 512,
        pCat, 512, 256, nullptr, nullptr, nullptr, nullptr, nullptr, nullptr, nullptr);

    // z,r = sigmoid([cat||prev] @ Uzr^T + bg)  (1-term, BK64)
    mma3<3, 1><<<dim3(4, MB), blk, SM1>>>(
        pCat, nullptr, 512, pPrev, nullptr, 256, 512,
        pUzr, nullptr, 768, 768,
        nullptr, 0, 0, bg, prev, pZ, pRh, nullptr, nullptr, nullptr);

    // n GEMM + hidden + fused predict  (1-term, BK64)
    mma3<4, 1><<<dim3(2, MB), blk, SM1>>>(
        pCat, nullptr, 512, pRh, nullptr, 256, 512,
        pUn, nullptr, 768, 768,
        nullptr, 0, 0, bg, prev, pZ, nullptr, out_hidden, Wp, out_pred);
}